// round 1
// baseline (speedup 1.0000x reference)
#include <cuda_runtime.h>
#include <cuda_bf16.h>
#include <math.h>

// Problem constants (fixed by the dataset)
#define LEN    21760
#define BATCH  2
#define MTOK   (BATCH * LEN)          // 43520
#define DMODEL 256
#define DFFN   1024
#define NHEADS 8
#define DHEAD  32
#define LNEPS  1e-5f

// ---------------------------------------------------------------------------
// Scratch (device globals — no allocation)
// ---------------------------------------------------------------------------
__device__ float g_value[(size_t)MTOK * DMODEL];
__device__ float g_off  [(size_t)MTOK * DMODEL];
__device__ float g_attn [(size_t)MTOK * 128];
__device__ float g_samp [(size_t)MTOK * DMODEL];
__device__ float g_x    [(size_t)MTOK * DMODEL];
__device__ float g_y    [(size_t)MTOK * DMODEL];
__device__ float g_h    [(size_t)MTOK * DFFN];

// ---------------------------------------------------------------------------
// GEMM: C[M,N] = (A (+A2))[M,K] @ W[K,N] + bias, optional relu, optional
// row-mask-zeroing.  M = 43520 fixed (gridDim.y = 340), BM=BN=128, BK=8,
// 256 threads, 8x8 micro-tile per thread.  M,N,K all multiples of tile dims.
// ---------------------------------------------------------------------------
__global__ __launch_bounds__(256, 2)
void gemm128(const float* __restrict__ A, const float* __restrict__ A2,
             const float* __restrict__ W, const float* __restrict__ bias,
             const unsigned char* __restrict__ mask,
             float* __restrict__ C, int K, int N, int relu)
{
    __shared__ float As[8][128];
    __shared__ float Bs[8][128];

    const int tid  = threadIdx.x;
    const int row0 = blockIdx.y * 128;
    const int col0 = blockIdx.x * 128;

    const int arow = tid >> 1;            // 0..127
    const int acol = (tid & 1) * 4;       // 0 or 4
    const int brow = tid >> 5;            // 0..7
    const int bcol = (tid & 31) * 4;      // 0..124

    const int tx = tid & 15;              // output col group
    const int ty = tid >> 4;              // output row group

    float acc[8][8];
#pragma unroll
    for (int i = 0; i < 8; i++)
#pragma unroll
        for (int j = 0; j < 8; j++) acc[i][j] = 0.f;

    const float* aptr  = A  + (size_t)(row0 + arow) * K + acol;
    const float* aptr2 = A2 ? A2 + (size_t)(row0 + arow) * K + acol : nullptr;

    for (int k0 = 0; k0 < K; k0 += 8) {
        float4 av = *(const float4*)(aptr + k0);
        if (aptr2) {
            float4 a2 = *(const float4*)(aptr2 + k0);
            av.x += a2.x; av.y += a2.y; av.z += a2.z; av.w += a2.w;
        }
        As[acol + 0][arow] = av.x;
        As[acol + 1][arow] = av.y;
        As[acol + 2][arow] = av.z;
        As[acol + 3][arow] = av.w;

        float4 bv = *(const float4*)(W + (size_t)(k0 + brow) * N + col0 + bcol);
        *(float4*)&Bs[brow][bcol] = bv;

        __syncthreads();
#pragma unroll
        for (int k = 0; k < 8; k++) {
            float ar[8], br[8];
            *(float4*)&ar[0] = *(const float4*)&As[k][ty * 8];
            *(float4*)&ar[4] = *(const float4*)&As[k][ty * 8 + 4];
            *(float4*)&br[0] = *(const float4*)&Bs[k][tx * 8];
            *(float4*)&br[4] = *(const float4*)&Bs[k][tx * 8 + 4];
#pragma unroll
            for (int i = 0; i < 8; i++)
#pragma unroll
                for (int j = 0; j < 8; j++)
                    acc[i][j] = fmaf(ar[i], br[j], acc[i][j]);
        }
        __syncthreads();
    }

    const int col = col0 + tx * 8;
    float bb[8];
#pragma unroll
    for (int j = 0; j < 8; j++) bb[j] = bias[col + j];

#pragma unroll
    for (int i = 0; i < 8; i++) {
        const int row = row0 + ty * 8 + i;
        float v[8];
#pragma unroll
        for (int j = 0; j < 8; j++) {
            float t = acc[i][j] + bb[j];
            if (relu) t = fmaxf(t, 0.f);
            v[j] = t;
        }
        if (mask && mask[row]) {
#pragma unroll
            for (int j = 0; j < 8; j++) v[j] = 0.f;
        }
        float* cp = C + (size_t)row * N + col;
        *(float4*)(cp)     = *(float4*)&v[0];
        *(float4*)(cp + 4) = *(float4*)&v[4];
    }
}

// ---------------------------------------------------------------------------
// Deformable-attention sampling.  One warp per (batch, token, head);
// lane = channel (0..31).  Every corner gather is a coalesced 128B segment.
// ---------------------------------------------------------------------------
__global__ __launch_bounds__(256)
void samp_kernel(const float* __restrict__ value, const float* __restrict__ attn,
                 const float* __restrict__ off,   const float* __restrict__ ref,
                 float* __restrict__ out)
{
    const int gw   = (blockIdx.x * blockDim.x + threadIdx.x) >> 5;
    const int lane = threadIdx.x & 31;
    if (gw >= MTOK * NHEADS) return;

    const int h  = gw & 7;
    const int bl = gw >> 3;          // b*LEN + t
    const int b  = bl / LEN;

    // softmax over 16 attention logits (redundant across lanes; cheap)
    const float* al = attn + (size_t)bl * 128 + h * 16;
    float w[16];
    float m = -1e30f;
#pragma unroll
    for (int i = 0; i < 16; i++) { w[i] = al[i]; m = fmaxf(m, w[i]); }
    float s = 0.f;
#pragma unroll
    for (int i = 0; i < 16; i++) { w[i] = __expf(w[i] - m); s += w[i]; }
    const float inv = 1.f / s;

    const float* op = off + (size_t)bl * 256 + h * 32;
    const float* rp = ref + (size_t)bl * 8;

    const int   Hs[4] = {128, 64, 32, 16};
    const int   Ss[4] = {0, 16384, 20480, 21504};

    float acc = 0.f;
#pragma unroll
    for (int l = 0; l < 4; l++) {
        const int   Hl = Hs[l], Wl = Hs[l];
        const float fH = (float)Hl, fW = (float)Wl;
        const float rx = rp[l * 2 + 0];
        const float ry = rp[l * 2 + 1];
        const float* vbase = value + ((size_t)(b * LEN + Ss[l])) * 256 + h * 32 + lane;
#pragma unroll
        for (int p = 0; p < 4; p++) {
            const float ox = op[l * 8 + p * 2 + 0];
            const float oy = op[l * 8 + p * 2 + 1];
            const float lx = rx + ox / fW;
            const float ly = ry + oy / fH;
            const float x  = lx * fW - 0.5f;
            const float y  = ly * fH - 0.5f;
            const float x0f = floorf(x), y0f = floorf(y);
            const float dx = x - x0f, dy = y - y0f;
            const int   x0 = (int)x0f, y0 = (int)y0f;
            const float aw = w[l * 4 + p] * inv;

            float psum = 0.f;
#pragma unroll
            for (int c = 0; c < 4; c++) {
                const int xi = x0 + (c & 1);
                const int yi = y0 + (c >> 1);
                float cw = ((c & 1) ? dx : (1.f - dx)) * ((c >> 1) ? dy : (1.f - dy));
                const bool valid = (xi >= 0) & (xi < Wl) & (yi >= 0) & (yi < Hl);
                const int xc = min(max(xi, 0), Wl - 1);
                const int yc = min(max(yi, 0), Hl - 1);
                const float v = vbase[(size_t)(yc * Wl + xc) * 256];
                psum += v * (valid ? cw : 0.f);
            }
            acc += aw * psum;
        }
    }
    out[(size_t)bl * 256 + h * 32 + lane] = acc;
}

// ---------------------------------------------------------------------------
// LayerNorm over 256 channels of (a + b): one warp per token.
// ---------------------------------------------------------------------------
__global__ __launch_bounds__(256)
void ln_kernel(const float* __restrict__ a, const float* __restrict__ b,
               const float* __restrict__ g, const float* __restrict__ beta,
               float* __restrict__ out)
{
    const int tok  = (blockIdx.x * blockDim.x + threadIdx.x) >> 5;
    const int lane = threadIdx.x & 31;
    if (tok >= MTOK) return;

    const float* pa = a + (size_t)tok * 256;
    const float* pb = b + (size_t)tok * 256;
    float v[8];
    float sum = 0.f;
#pragma unroll
    for (int i = 0; i < 8; i++) {
        const int c = lane + i * 32;
        v[i] = pa[c] + pb[c];
        sum += v[i];
    }
#pragma unroll
    for (int o = 16; o > 0; o >>= 1) sum += __shfl_xor_sync(0xffffffffu, sum, o);
    const float mean = sum * (1.f / 256.f);

    float vs = 0.f;
#pragma unroll
    for (int i = 0; i < 8; i++) {
        const float d = v[i] - mean;
        vs += d * d;
    }
#pragma unroll
    for (int o = 16; o > 0; o >>= 1) vs += __shfl_xor_sync(0xffffffffu, vs, o);
    const float rinv = rsqrtf(vs * (1.f / 256.f) + LNEPS);

#pragma unroll
    for (int i = 0; i < 8; i++) {
        const int c = lane + i * 32;
        out[(size_t)tok * 256 + c] = (v[i] - mean) * rinv * g[c] + beta[c];
    }
}

// ---------------------------------------------------------------------------
// Launch
// ---------------------------------------------------------------------------
extern "C" void kernel_launch(void* const* d_in, const int* in_sizes, int n_in,
                              void* d_out, int out_size)
{
    const float* src  = (const float*)d_in[0];
    const float* pos  = (const float*)d_in[1];
    const float* ref  = (const float*)d_in[2];
    const unsigned char* mask = (const unsigned char*)d_in[5];
    const float* w_off  = (const float*)d_in[6];
    const float* b_off  = (const float*)d_in[7];
    const float* w_attn = (const float*)d_in[8];
    const float* b_attn = (const float*)d_in[9];
    const float* w_val  = (const float*)d_in[10];
    const float* b_val  = (const float*)d_in[11];
    const float* w_out  = (const float*)d_in[12];
    const float* b_out  = (const float*)d_in[13];
    const float* ln1g   = (const float*)d_in[14];
    const float* ln1b   = (const float*)d_in[15];
    const float* w1     = (const float*)d_in[16];
    const float* b1     = (const float*)d_in[17];
    const float* w2     = (const float*)d_in[18];
    const float* b2     = (const float*)d_in[19];
    const float* ln2g   = (const float*)d_in[20];
    const float* ln2b   = (const float*)d_in[21];
    float* out = (float*)d_out;

    float *p_value, *p_off, *p_attn, *p_samp, *p_x, *p_y, *p_h;
    cudaGetSymbolAddress((void**)&p_value, g_value);
    cudaGetSymbolAddress((void**)&p_off,   g_off);
    cudaGetSymbolAddress((void**)&p_attn,  g_attn);
    cudaGetSymbolAddress((void**)&p_samp,  g_samp);
    cudaGetSymbolAddress((void**)&p_x,     g_x);
    cudaGetSymbolAddress((void**)&p_y,     g_y);
    cudaGetSymbolAddress((void**)&p_h,     g_h);

    const int MY = MTOK / 128;   // 340

    // value = src @ w_val + b_val (masked)
    gemm128<<<dim3(2, MY), 256>>>(src, nullptr, w_val, b_val, mask, p_value, 256, 256, 0);
    // off = (src+pos) @ w_off + b_off
    gemm128<<<dim3(2, MY), 256>>>(src, pos, w_off, b_off, nullptr, p_off, 256, 256, 0);
    // attn logits = (src+pos) @ w_attn + b_attn
    gemm128<<<dim3(1, MY), 256>>>(src, pos, w_attn, b_attn, nullptr, p_attn, 256, 128, 0);
    // deformable sampling
    samp_kernel<<<(MTOK * NHEADS) / 8, 256>>>(p_value, p_attn, p_off, ref, p_samp);
    // attn_out = samp @ w_out + b_out
    gemm128<<<dim3(2, MY), 256>>>(p_samp, nullptr, w_out, b_out, nullptr, p_y, 256, 256, 0);
    // x = LN(src + attn_out)
    ln_kernel<<<MTOK / 8, 256>>>(src, p_y, ln1g, ln1b, p_x);
    // h = relu(x @ w1 + b1)
    gemm128<<<dim3(8, MY), 256>>>(p_x, nullptr, w1, b1, nullptr, p_h, 256, 1024, 1);
    // y = h @ w2 + b2
    gemm128<<<dim3(2, MY), 256>>>(p_h, nullptr, w2, b2, nullptr, p_y, 1024, 256, 0);
    // out = LN(x + y)
    ln_kernel<<<MTOK / 8, 256>>>(p_x, p_y, ln2g, ln2b, out);
}

// round 3
// speedup vs baseline: 2.0933x; 2.0933x over previous
#include <cuda_runtime.h>
#include <cuda_bf16.h>
#include <cstdint>
#include <math.h>

// Problem constants (fixed by the dataset)
#define LEN    21760
#define BATCH  2
#define MTOK   (BATCH * LEN)          // 43520
#define DMODEL 256
#define DFFN   1024
#define NHEADS 8
#define DHEAD  32
#define LNEPS  1e-5f

// ---------------------------------------------------------------------------
// Scratch (device globals — no allocation)
// ---------------------------------------------------------------------------
__device__ float g_q    [(size_t)MTOK * DMODEL];
__device__ float g_value[(size_t)MTOK * DMODEL];
__device__ float g_off  [(size_t)MTOK * DMODEL];
__device__ float g_attn [(size_t)MTOK * 128];
__device__ float g_samp [(size_t)MTOK * DMODEL];
__device__ float g_x    [(size_t)MTOK * DMODEL];
__device__ float g_y    [(size_t)MTOK * DMODEL];
__device__ float g_h    [(size_t)MTOK * DFFN];
// transposed weights [N, K] (K-major)
__device__ float g_wtval [256 * 256];
__device__ float g_wtoff [256 * 256];
__device__ float g_wtattn[128 * 256];
__device__ float g_wtout [256 * 256];
__device__ float g_wt1   [1024 * 256];
__device__ float g_wt2   [256 * 1024];

// ---------------------------------------------------------------------------
// Small helpers
// ---------------------------------------------------------------------------
__device__ __forceinline__ uint32_t smem_u32(const void* p) {
    uint32_t a;
    asm("{ .reg .u64 t; cvta.to.shared.u64 t, %1; cvt.u32.u64 %0, t; }" : "=r"(a) : "l"(p));
    return a;
}
__device__ __forceinline__ uint32_t f2tf32(float f) {
    uint32_t u;
    asm("cvt.rna.tf32.f32 %0, %1;" : "=r"(u) : "f"(f));
    return u;
}
__device__ __forceinline__ void cp_async16(uint32_t saddr, const void* gaddr) {
    asm volatile("cp.async.cg.shared.global [%0], [%1], 16;" :: "r"(saddr), "l"(gaddr));
}
__device__ __forceinline__ void cp_commit() { asm volatile("cp.async.commit_group;"); }

__device__ __forceinline__ void mma_tf32(float* d, const uint32_t* a, const uint32_t* b) {
    asm volatile(
        "mma.sync.aligned.m16n8k8.row.col.f32.tf32.tf32.f32 "
        "{%0,%1,%2,%3}, {%4,%5,%6,%7}, {%8,%9}, {%0,%1,%2,%3};"
        : "+f"(d[0]), "+f"(d[1]), "+f"(d[2]), "+f"(d[3])
        : "r"(a[0]), "r"(a[1]), "r"(a[2]), "r"(a[3]), "r"(b[0]), "r"(b[1]));
}

// ---------------------------------------------------------------------------
// q = src + pos   (float4 elementwise)
// ---------------------------------------------------------------------------
__global__ __launch_bounds__(256)
void add_kernel(const float* __restrict__ a, const float* __restrict__ b, float* __restrict__ o, int n4)
{
    const int i = blockIdx.x * blockDim.x + threadIdx.x;
    if (i >= n4) return;
    float4 x = ((const float4*)a)[i];
    float4 y = ((const float4*)b)[i];
    x.x += y.x; x.y += y.y; x.z += y.z; x.w += y.w;
    ((float4*)o)[i] = x;
}

// ---------------------------------------------------------------------------
// Weight transpose: out[n*K + k] = in[k*N + n]
// ---------------------------------------------------------------------------
__global__ void transpose_w(const float* __restrict__ in, float* __restrict__ out, int K, int N)
{
    __shared__ float t[32][33];
    const int n0 = blockIdx.x * 32, k0 = blockIdx.y * 32;
    const int tx = threadIdx.x, ty = threadIdx.y;
#pragma unroll
    for (int j = 0; j < 32; j += 8)
        t[ty + j][tx] = in[(size_t)(k0 + ty + j) * N + n0 + tx];
    __syncthreads();
#pragma unroll
    for (int j = 0; j < 32; j += 8)
        out[(size_t)(n0 + ty + j) * K + k0 + tx] = t[tx][ty + j];
}

// ---------------------------------------------------------------------------
// tf32 mma.sync GEMM:  C[M,N] = A[M,K] @ BT[N,K]^T + bias, opt relu/mask.
// BM=BN=128, BK=32, 256 threads (8 warps: 2 x 4), warp = 64x32,
// m16n8k8 tiles 4x4 per warp, K in 4 sub-steps. cp.async double buffer.
// Smem: As[2][128][36], Bs[2][128][36] (pad 4 -> conflict-free everywhere).
// ---------------------------------------------------------------------------
#define LDT 36
#define ABYTES (128 * LDT * 4)

__global__ __launch_bounds__(256, 2)
void gemm_mma(const float* __restrict__ A, const float* __restrict__ BT,
              const float* __restrict__ bias, const unsigned char* __restrict__ mask,
              float* __restrict__ C, int K, int N, int relu)
{
    extern __shared__ float sm[];
    float* As = sm;                    // [2][128][36]
    float* Bs = sm + 2 * 128 * LDT;    // [2][128][36]

    const int tid  = threadIdx.x;
    const int wid  = tid >> 5;
    const int lane = tid & 31;
    const int gr   = lane >> 2;        // 0..7
    const int gc   = lane & 3;         // 0..3
    const int wm   = wid & 1;          // warp row (64 rows each)
    const int wn   = wid >> 1;         // warp col (32 cols each)
    const int row0 = blockIdx.y * 128;
    const int col0 = blockIdx.x * 128;

    const uint32_t sA = smem_u32(As);
    const uint32_t sB = smem_u32(Bs);

    float acc[4][4][4];
#pragma unroll
    for (int mt = 0; mt < 4; mt++)
#pragma unroll
        for (int nt = 0; nt < 4; nt++)
#pragma unroll
            for (int r = 0; r < 4; r++) acc[mt][nt][r] = 0.f;

    const int nch = K >> 5;

    // loader thread mapping: idx = it*256+tid; row = idx>>3, c4 = (idx&7)*4
    const int lrow = tid >> 3;          // advances by 32 per it
    const int lc4  = (tid & 7) << 2;

    const float* Ab = A  + (size_t)(row0 + lrow) * K + lc4;
    const float* Bb = BT + (size_t)(col0 + lrow) * K + lc4;

#define LOAD_CHUNK(i) do {                                                        \
        const int _k0 = (i) * 32;                                                 \
        const uint32_t _abase = sA + ((i) & 1) * ABYTES;                          \
        const uint32_t _bbase = sB + ((i) & 1) * ABYTES;                          \
        _Pragma("unroll")                                                         \
        for (int it = 0; it < 4; it++) {                                          \
            const int r = it * 32;                                                \
            cp_async16(_abase + (uint32_t)(((lrow + r) * LDT + lc4) * 4),         \
                       Ab + (size_t)r * K + _k0);                                 \
            cp_async16(_bbase + (uint32_t)(((lrow + r) * LDT + lc4) * 4),         \
                       Bb + (size_t)r * K + _k0);                                 \
        }                                                                         \
        cp_commit();                                                              \
    } while (0)

    LOAD_CHUNK(0);

    for (int i = 0; i < nch; i++) {
        if (i + 1 < nch) {
            LOAD_CHUNK(i + 1);
            asm volatile("cp.async.wait_group 1;" ::: "memory");
        } else {
            asm volatile("cp.async.wait_group 0;" ::: "memory");
        }
        __syncthreads();

        const float* Ac = As + (i & 1) * (128 * LDT);
        const float* Bc = Bs + (i & 1) * (128 * LDT);

#pragma unroll
        for (int ks = 0; ks < 4; ks++) {
            const int kk = ks * 8;
            uint32_t af[4][4];
#pragma unroll
            for (int mt = 0; mt < 4; mt++) {
                const int r = wm * 64 + mt * 16 + gr;
                af[mt][0] = f2tf32(Ac[(r)     * LDT + kk + gc]);
                af[mt][1] = f2tf32(Ac[(r + 8) * LDT + kk + gc]);
                af[mt][2] = f2tf32(Ac[(r)     * LDT + kk + gc + 4]);
                af[mt][3] = f2tf32(Ac[(r + 8) * LDT + kk + gc + 4]);
            }
            uint32_t bf[4][2];
#pragma unroll
            for (int nt = 0; nt < 4; nt++) {
                const int r = wn * 32 + nt * 8 + gr;
                bf[nt][0] = f2tf32(Bc[r * LDT + kk + gc]);
                bf[nt][1] = f2tf32(Bc[r * LDT + kk + gc + 4]);
            }
#pragma unroll
            for (int mt = 0; mt < 4; mt++)
#pragma unroll
                for (int nt = 0; nt < 4; nt++)
                    mma_tf32(acc[mt][nt], af[mt], bf[nt]);
        }
        __syncthreads();
    }

    // epilogue: c0,c1 -> (row, col+0/1); c2,c3 -> (row+8, col+0/1)
#pragma unroll
    for (int mt = 0; mt < 4; mt++) {
        const int r0 = row0 + wm * 64 + mt * 16 + gr;
#pragma unroll
        for (int nt = 0; nt < 4; nt++) {
            const int col = col0 + wn * 32 + nt * 8 + gc * 2;
            const float b0 = __ldg(bias + col);
            const float b1 = __ldg(bias + col + 1);
            float v0 = acc[mt][nt][0] + b0, v1 = acc[mt][nt][1] + b1;
            float v2 = acc[mt][nt][2] + b0, v3 = acc[mt][nt][3] + b1;
            if (relu) {
                v0 = fmaxf(v0, 0.f); v1 = fmaxf(v1, 0.f);
                v2 = fmaxf(v2, 0.f); v3 = fmaxf(v3, 0.f);
            }
            if (mask) {
                if (mask[r0])     { v0 = v1 = 0.f; }
                if (mask[r0 + 8]) { v2 = v3 = 0.f; }
            }
            *(float2*)(C + (size_t)r0 * N + col)       = make_float2(v0, v1);
            *(float2*)(C + (size_t)(r0 + 8) * N + col) = make_float2(v2, v3);
        }
    }
}

// ---------------------------------------------------------------------------
// Deformable-attention sampling.  One warp per (batch, token, head);
// lane = channel.  Scalar work de-duplicated across lanes via shfl.
// ---------------------------------------------------------------------------
__global__ __launch_bounds__(256)
void samp_kernel(const float* __restrict__ value, const float* __restrict__ attn,
                 const float* __restrict__ off,   const float* __restrict__ ref,
                 float* __restrict__ out)
{
    const int gw   = (blockIdx.x * blockDim.x + threadIdx.x) >> 5;
    const int lane = threadIdx.x & 31;
    if (gw >= MTOK * NHEADS) return;

    const int h  = gw & 7;
    const int bl = gw >> 3;
    const int b  = (bl >= LEN) ? 1 : 0;

    // softmax across lanes (lanes 0..15 hold the 16 logits)
    float logit = (lane < 16) ? __ldg(attn + bl * 128 + h * 16 + lane) : -1e30f;
    float m = logit;
#pragma unroll
    for (int o = 16; o > 0; o >>= 1) m = fmaxf(m, __shfl_xor_sync(0xffffffffu, m, o));
    float e = (lane < 16) ? __expf(logit - m) : 0.f;
    float s = e;
#pragma unroll
    for (int o = 16; o > 0; o >>= 1) s += __shfl_xor_sync(0xffffffffu, s, o);
    const float wn = e / s;

    const float ov = __ldg(off + bl * 256 + h * 32 + lane);  // 32 offsets, one per lane
    const float rv = (lane < 8) ? __ldg(ref + bl * 8 + lane) : 0.f;

    const int Hs[4] = {128, 64, 32, 16};
    const int Ss[4] = {0, 16384, 20480, 21504};

    float acc = 0.f;
#pragma unroll
    for (int l = 0; l < 4; l++) {
        const int   Wl = Hs[l];
        const float fW = (float)Wl;
        const float rx = __shfl_sync(0xffffffffu, rv, 2 * l);
        const float ry = __shfl_sync(0xffffffffu, rv, 2 * l + 1);
        const float* vb = value + (b * LEN + Ss[l]) * 256 + h * 32 + lane;
#pragma unroll
        for (int p = 0; p < 4; p++) {
            const float ox = __shfl_sync(0xffffffffu, ov, l * 8 + p * 2);
            const float oy = __shfl_sync(0xffffffffu, ov, l * 8 + p * 2 + 1);
            const float aw = __shfl_sync(0xffffffffu, wn, l * 4 + p);
            const float x  = fmaf(rx, fW, ox) - 0.5f;
            const float y  = fmaf(ry, fW, oy) - 0.5f;
            const float x0f = floorf(x), y0f = floorf(y);
            const float dx = x - x0f, dy = y - y0f;
            const int   x0 = (int)x0f, y0 = (int)y0f;

            float psum = 0.f;
#pragma unroll
            for (int c = 0; c < 4; c++) {
                const int xi = x0 + (c & 1);
                const int yi = y0 + (c >> 1);
                const float cw = ((c & 1) ? dx : 1.f - dx) * ((c >> 1) ? dy : 1.f - dy);
                const bool valid = (xi >= 0) & (xi < Wl) & (yi >= 0) & (yi < Wl);
                const int xc = min(max(xi, 0), Wl - 1);
                const int yc = min(max(yi, 0), Wl - 1);
                const float v = __ldg(vb + (yc * Wl + xc) * 256);
                psum = fmaf(v, valid ? cw : 0.f, psum);
            }
            acc = fmaf(aw, psum, acc);
        }
    }
    out[bl * 256 + h * 32 + lane] = acc;
}

// ---------------------------------------------------------------------------
// LayerNorm over 256 channels of (a + b): one warp per token.
// ---------------------------------------------------------------------------
__global__ __launch_bounds__(256)
void ln_kernel(const float* __restrict__ a, const float* __restrict__ b,
               const float* __restrict__ g, const float* __restrict__ beta,
               float* __restrict__ out)
{
    const int tok  = (blockIdx.x * blockDim.x + threadIdx.x) >> 5;
    const int lane = threadIdx.x & 31;
    if (tok >= MTOK) return;

    const float* pa = a + (size_t)tok * 256;
    const float* pb = b + (size_t)tok * 256;
    float v[8];
    float sum = 0.f;
#pragma unroll
    for (int i = 0; i < 8; i++) {
        const int c = lane + i * 32;
        v[i] = pa[c] + pb[c];
        sum += v[i];
    }
#pragma unroll
    for (int o = 16; o > 0; o >>= 1) sum += __shfl_xor_sync(0xffffffffu, sum, o);
    const float mean = sum * (1.f / 256.f);

    float vs = 0.f;
#pragma unroll
    for (int i = 0; i < 8; i++) { const float d = v[i] - mean; vs += d * d; }
#pragma unroll
    for (int o = 16; o > 0; o >>= 1) vs += __shfl_xor_sync(0xffffffffu, vs, o);
    const float rinv = rsqrtf(vs * (1.f / 256.f) + LNEPS);

#pragma unroll
    for (int i = 0; i < 8; i++) {
        const int c = lane + i * 32;
        out[(size_t)tok * 256 + c] = (v[i] - mean) * rinv * g[c] + beta[c];
    }
}

// ---------------------------------------------------------------------------
// Launch
// ---------------------------------------------------------------------------
extern "C" void kernel_launch(void* const* d_in, const int* in_sizes, int n_in,
                              void* d_out, int out_size)
{
    const float* src  = (const float*)d_in[0];
    const float* pos  = (const float*)d_in[1];
    const float* ref  = (const float*)d_in[2];
    const unsigned char* mask = (const unsigned char*)d_in[5];
    const float* w_off  = (const float*)d_in[6];
    const float* b_off  = (const float*)d_in[7];
    const float* w_attn = (const float*)d_in[8];
    const float* b_attn = (const float*)d_in[9];
    const float* w_val  = (const float*)d_in[10];
    const float* b_val  = (const float*)d_in[11];
    const float* w_out  = (const float*)d_in[12];
    const float* b_out  = (const float*)d_in[13];
    const float* ln1g   = (const float*)d_in[14];
    const float* ln1b   = (const float*)d_in[15];
    const float* w1     = (const float*)d_in[16];
    const float* b1     = (const float*)d_in[17];
    const float* w2     = (const float*)d_in[18];
    const float* b2     = (const float*)d_in[19];
    const float* ln2g   = (const float*)d_in[20];
    const float* ln2b   = (const float*)d_in[21];
    float* out = (float*)d_out;

    float *p_q, *p_value, *p_off, *p_attn, *p_samp, *p_x, *p_y, *p_h;
    float *t_val, *t_off, *t_attn, *t_out, *t_w1, *t_w2;
    cudaGetSymbolAddress((void**)&p_q,     g_q);
    cudaGetSymbolAddress((void**)&p_value, g_value);
    cudaGetSymbolAddress((void**)&p_off,   g_off);
    cudaGetSymbolAddress((void**)&p_attn,  g_attn);
    cudaGetSymbolAddress((void**)&p_samp,  g_samp);
    cudaGetSymbolAddress((void**)&p_x,     g_x);
    cudaGetSymbolAddress((void**)&p_y,     g_y);
    cudaGetSymbolAddress((void**)&p_h,     g_h);
    cudaGetSymbolAddress((void**)&t_val,   g_wtval);
    cudaGetSymbolAddress((void**)&t_off,   g_wtoff);
    cudaGetSymbolAddress((void**)&t_attn,  g_wtattn);
    cudaGetSymbolAddress((void**)&t_out,   g_wtout);
    cudaGetSymbolAddress((void**)&t_w1,    g_wt1);
    cudaGetSymbolAddress((void**)&t_w2,    g_wt2);

    const int SMEM = 2 * 2 * 128 * LDT * 4;   // 73728 bytes
    static int cfg_done = 0;
    cudaFuncSetAttribute(gemm_mma, cudaFuncAttributeMaxDynamicSharedMemorySize, SMEM);
    (void)cfg_done;

    const int MY = MTOK / 128;   // 340
    dim3 tb(32, 8);

    // q = src + pos
    add_kernel<<<(MTOK * 256 / 4 + 255) / 256, 256>>>(src, pos, p_q, MTOK * 256 / 4);

    // transpose weights to K-major [N, K]
    transpose_w<<<dim3(256/32, 256/32), tb>>>(w_val,  t_val,  256, 256);
    transpose_w<<<dim3(256/32, 256/32), tb>>>(w_off,  t_off,  256, 256);
    transpose_w<<<dim3(128/32, 256/32), tb>>>(w_attn, t_attn, 256, 128);
    transpose_w<<<dim3(256/32, 256/32), tb>>>(w_out,  t_out,  256, 256);
    transpose_w<<<dim3(1024/32, 256/32), tb>>>(w1,    t_w1,   256, 1024);
    transpose_w<<<dim3(256/32, 1024/32), tb>>>(w2,    t_w2,   1024, 256);

    // value = src @ w_val + b_val (masked rows -> 0)
    gemm_mma<<<dim3(2, MY), 256, SMEM>>>(src, t_val, b_val, mask, p_value, 256, 256, 0);
    // off = q @ w_off + b_off
    gemm_mma<<<dim3(2, MY), 256, SMEM>>>(p_q, t_off, b_off, nullptr, p_off, 256, 256, 0);
    // attn logits = q @ w_attn + b_attn
    gemm_mma<<<dim3(1, MY), 256, SMEM>>>(p_q, t_attn, b_attn, nullptr, p_attn, 256, 128, 0);
    // deformable sampling (softmax fused)
    samp_kernel<<<(MTOK * NHEADS) / 8, 256>>>(p_value, p_attn, p_off, ref, p_samp);
    // attn_out = samp @ w_out + b_out
    gemm_mma<<<dim3(2, MY), 256, SMEM>>>(p_samp, t_out, b_out, nullptr, p_y, 256, 256, 0);
    // x = LN(src + attn_out)
    ln_kernel<<<MTOK / 8, 256>>>(src, p_y, ln1g, ln1b, p_x);
    // h = relu(x @ w1 + b1)
    gemm_mma<<<dim3(8, MY), 256, SMEM>>>(p_x, t_w1, b1, nullptr, p_h, 256, 1024, 1);
    // y = h @ w2 + b2
    gemm_mma<<<dim3(2, MY), 256, SMEM>>>(p_h, t_w2, b2, nullptr, p_y, 1024, 256, 0);
    // out = LN(x + y)
    ln_kernel<<<MTOK / 8, 256>>>(p_x, p_y, ln2g, ln2b, out);
}

// round 4
// speedup vs baseline: 2.5968x; 1.2405x over previous
#include <cuda_runtime.h>
#include <cuda_bf16.h>
#include <cstdint>
#include <math.h>

// Problem constants (fixed by the dataset)
#define LEN    21760
#define BATCH  2
#define MTOK   (BATCH * LEN)          // 43520
#define DMODEL 256
#define DFFN   1024
#define NHEADS 8
#define LNEPS  1e-5f

typedef __nv_bfloat16 bf16;
typedef __nv_bfloat162 bf162;

// ---------------------------------------------------------------------------
// Scratch (device globals — no allocation)
// ---------------------------------------------------------------------------
__device__ bf16  g_srcb [(size_t)MTOK * DMODEL];
__device__ bf16  g_qb   [(size_t)MTOK * DMODEL];
__device__ bf16  g_value[(size_t)MTOK * DMODEL];
__device__ float g_off  [(size_t)MTOK * DMODEL];
__device__ float g_attn [(size_t)MTOK * 128];
__device__ bf16  g_samp [(size_t)MTOK * DMODEL];
__device__ float g_x    [(size_t)MTOK * DMODEL];
__device__ bf16  g_xb   [(size_t)MTOK * DMODEL];
__device__ float g_y    [(size_t)MTOK * DMODEL];
__device__ bf16  g_h    [(size_t)MTOK * DFFN];
// transposed bf16 weights [N, K] (K-major)
__device__ bf16 g_wtval [256 * 256];
__device__ bf16 g_wtoff [256 * 256];
__device__ bf16 g_wtattn[128 * 256];
__device__ bf16 g_wtout [256 * 256];
__device__ bf16 g_wt1   [1024 * 256];
__device__ bf16 g_wt2   [256 * 1024];

// ---------------------------------------------------------------------------
// Helpers
// ---------------------------------------------------------------------------
__device__ __forceinline__ uint32_t smem_u32(const void* p) {
    uint32_t a;
    asm("{ .reg .u64 t; cvta.to.shared.u64 t, %1; cvt.u32.u64 %0, t; }" : "=r"(a) : "l"(p));
    return a;
}
__device__ __forceinline__ void cp_async16(uint32_t saddr, const void* gaddr) {
    asm volatile("cp.async.cg.shared.global [%0], [%1], 16;" :: "r"(saddr), "l"(gaddr));
}
__device__ __forceinline__ void cp_commit() { asm volatile("cp.async.commit_group;"); }

__device__ __forceinline__ void mma_bf16(float* d, const uint32_t* a, const uint32_t* b) {
    asm volatile(
        "mma.sync.aligned.m16n8k16.row.col.f32.bf16.bf16.f32 "
        "{%0,%1,%2,%3}, {%4,%5,%6,%7}, {%8,%9}, {%0,%1,%2,%3};"
        : "+f"(d[0]), "+f"(d[1]), "+f"(d[2]), "+f"(d[3])
        : "r"(a[0]), "r"(a[1]), "r"(a[2]), "r"(a[3]), "r"(b[0]), "r"(b[1]));
}

// ---------------------------------------------------------------------------
// prep: srcb = bf16(src), qb = bf16(src + pos)      (per float4)
// ---------------------------------------------------------------------------
__global__ __launch_bounds__(256)
void prep_kernel(const float* __restrict__ src, const float* __restrict__ pos,
                 bf16* __restrict__ srcb, bf16* __restrict__ qb, int n4)
{
    const int i = blockIdx.x * blockDim.x + threadIdx.x;
    if (i >= n4) return;
    float4 s = ((const float4*)src)[i];
    float4 p = ((const float4*)pos)[i];
    bf162* sb = (bf162*)srcb + i * 2;
    bf162* qo = (bf162*)qb + i * 2;
    sb[0] = __floats2bfloat162_rn(s.x, s.y);
    sb[1] = __floats2bfloat162_rn(s.z, s.w);
    qo[0] = __floats2bfloat162_rn(s.x + p.x, s.y + p.y);
    qo[1] = __floats2bfloat162_rn(s.z + p.z, s.w + p.w);
}

// ---------------------------------------------------------------------------
// Weight transpose + convert: out[n*K + k] = bf16(in[k*N + n])
// ---------------------------------------------------------------------------
__global__ void transpose_w(const float* __restrict__ in, bf16* __restrict__ out, int K, int N)
{
    __shared__ float t[32][33];
    const int n0 = blockIdx.x * 32, k0 = blockIdx.y * 32;
    const int tx = threadIdx.x, ty = threadIdx.y;
#pragma unroll
    for (int j = 0; j < 32; j += 8)
        t[ty + j][tx] = in[(size_t)(k0 + ty + j) * N + n0 + tx];
    __syncthreads();
#pragma unroll
    for (int j = 0; j < 32; j += 8)
        out[(size_t)(n0 + ty + j) * K + k0 + tx] = __float2bfloat16(t[tx][ty + j]);
}

// ---------------------------------------------------------------------------
// bf16 mma GEMM:  C[M,N] = A[M,K] @ BT[N,K]^T + bias, opt relu/mask.
// BM=BN=128, BK=64, 256 threads (8 warps 2x4), warp=64x32, m16n8k16 4x4,
// K sub-steps of 16.  cp.async double buffer.  Smem rows padded to 72 bf16.
// Outputs: Cf (fp32) and/or Cb (bf16), either may be null.
// ---------------------------------------------------------------------------
#define LDT 72                       // bf16 elements per smem row (144 B)
#define TBYTES (128 * LDT * 2)       // one tile buffer

__global__ __launch_bounds__(256, 2)
void gemm_bf(const bf16* __restrict__ A, const bf16* __restrict__ BT,
             const float* __restrict__ bias, const unsigned char* __restrict__ mask,
             float* __restrict__ Cf, bf16* __restrict__ Cb, int K, int N, int relu)
{
    extern __shared__ bf16 sm[];
    bf16* As = sm;                    // [2][128][72]
    bf16* Bs = sm + 2 * 128 * LDT;

    const int tid  = threadIdx.x;
    const int wid  = tid >> 5;
    const int lane = tid & 31;
    const int gr   = lane >> 2;
    const int gc   = lane & 3;
    const int wm   = wid & 1;
    const int wn   = wid >> 1;
    const int row0 = blockIdx.y * 128;
    const int col0 = blockIdx.x * 128;

    const uint32_t sA = smem_u32(As);
    const uint32_t sB = smem_u32(Bs);

    float acc[4][4][4];
#pragma unroll
    for (int mt = 0; mt < 4; mt++)
#pragma unroll
        for (int nt = 0; nt < 4; nt++)
#pragma unroll
            for (int r = 0; r < 4; r++) acc[mt][nt][r] = 0.f;

    const int nch = K >> 6;           // chunks of 64

    // loader: row = tid>>3 (+32/it), lc = (tid&7)*8 bf16 (16 B)
    const int lrow = tid >> 3;
    const int lc   = (tid & 7) << 3;

    const bf16* Ab = A  + (size_t)(row0 + lrow) * K + lc;
    const bf16* Bb = BT + (size_t)(col0 + lrow) * K + lc;

#define LOAD_CHUNK(i) do {                                                        \
        const int _k0 = (i) << 6;                                                 \
        const uint32_t _abase = sA + ((i) & 1) * TBYTES;                          \
        const uint32_t _bbase = sB + ((i) & 1) * TBYTES;                          \
        _Pragma("unroll")                                                         \
        for (int it = 0; it < 4; it++) {                                          \
            const int r = it * 32;                                                \
            cp_async16(_abase + (uint32_t)(((lrow + r) * LDT + lc) * 2),          \
                       Ab + (size_t)r * K + _k0);                                 \
            cp_async16(_bbase + (uint32_t)(((lrow + r) * LDT + lc) * 2),          \
                       Bb + (size_t)r * K + _k0);                                 \
        }                                                                         \
        cp_commit();                                                              \
    } while (0)

    LOAD_CHUNK(0);

    for (int i = 0; i < nch; i++) {
        if (i + 1 < nch) {
            LOAD_CHUNK(i + 1);
            asm volatile("cp.async.wait_group 1;" ::: "memory");
        } else {
            asm volatile("cp.async.wait_group 0;" ::: "memory");
        }
        __syncthreads();

        const bf16* Ac = As + (i & 1) * (128 * LDT);
        const bf16* Bc = Bs + (i & 1) * (128 * LDT);

#pragma unroll
        for (int ks = 0; ks < 4; ks++) {
            const int kk = ks * 16;
            uint32_t af[4][4];
#pragma unroll
            for (int mt = 0; mt < 4; mt++) {
                const int r = wm * 64 + mt * 16 + gr;
                af[mt][0] = *(const uint32_t*)&Ac[(r)     * LDT + kk + 2 * gc];
                af[mt][1] = *(const uint32_t*)&Ac[(r + 8) * LDT + kk + 2 * gc];
                af[mt][2] = *(const uint32_t*)&Ac[(r)     * LDT + kk + 8 + 2 * gc];
                af[mt][3] = *(const uint32_t*)&Ac[(r + 8) * LDT + kk + 8 + 2 * gc];
            }
            uint32_t bfr[4][2];
#pragma unroll
            for (int nt = 0; nt < 4; nt++) {
                const int r = wn * 32 + nt * 8 + gr;
                bfr[nt][0] = *(const uint32_t*)&Bc[r * LDT + kk + 2 * gc];
                bfr[nt][1] = *(const uint32_t*)&Bc[r * LDT + kk + 8 + 2 * gc];
            }
#pragma unroll
            for (int mt = 0; mt < 4; mt++)
#pragma unroll
                for (int nt = 0; nt < 4; nt++)
                    mma_bf16(acc[mt][nt], af[mt], bfr[nt]);
        }
        __syncthreads();
    }

    // epilogue
#pragma unroll
    for (int mt = 0; mt < 4; mt++) {
        const int r0 = row0 + wm * 64 + mt * 16 + gr;
        const bool m0 = mask && mask[r0];
        const bool m1 = mask && mask[r0 + 8];
#pragma unroll
        for (int nt = 0; nt < 4; nt++) {
            const int col = col0 + wn * 32 + nt * 8 + gc * 2;
            const float b0 = __ldg(bias + col);
            const float b1 = __ldg(bias + col + 1);
            float v0 = acc[mt][nt][0] + b0, v1 = acc[mt][nt][1] + b1;
            float v2 = acc[mt][nt][2] + b0, v3 = acc[mt][nt][3] + b1;
            if (relu) {
                v0 = fmaxf(v0, 0.f); v1 = fmaxf(v1, 0.f);
                v2 = fmaxf(v2, 0.f); v3 = fmaxf(v3, 0.f);
            }
            if (m0) { v0 = v1 = 0.f; }
            if (m1) { v2 = v3 = 0.f; }
            if (Cf) {
                *(float2*)(Cf + (size_t)r0 * N + col)       = make_float2(v0, v1);
                *(float2*)(Cf + (size_t)(r0 + 8) * N + col) = make_float2(v2, v3);
            }
            if (Cb) {
                *(bf162*)(Cb + (size_t)r0 * N + col)       = __floats2bfloat162_rn(v0, v1);
                *(bf162*)(Cb + (size_t)(r0 + 8) * N + col) = __floats2bfloat162_rn(v2, v3);
            }
        }
    }
}

// ---------------------------------------------------------------------------
// Deformable-attention sampling (value in bf16).  One warp per (token, head);
// lane = channel.  Softmax + scalar work deduplicated via shfl.
// ---------------------------------------------------------------------------
__global__ __launch_bounds__(256)
void samp_kernel(const bf16* __restrict__ value, const float* __restrict__ attn,
                 const float* __restrict__ off,  const float* __restrict__ ref,
                 bf16* __restrict__ out)
{
    const int gw   = (blockIdx.x * blockDim.x + threadIdx.x) >> 5;
    const int lane = threadIdx.x & 31;
    if (gw >= MTOK * NHEADS) return;

    const int h  = gw & 7;
    const int bl = gw >> 3;
    const int b  = (bl >= LEN) ? 1 : 0;

    float logit = (lane < 16) ? __ldg(attn + bl * 128 + h * 16 + lane) : -1e30f;
    float m = logit;
#pragma unroll
    for (int o = 16; o > 0; o >>= 1) m = fmaxf(m, __shfl_xor_sync(0xffffffffu, m, o));
    float e = (lane < 16) ? __expf(logit - m) : 0.f;
    float s = e;
#pragma unroll
    for (int o = 16; o > 0; o >>= 1) s += __shfl_xor_sync(0xffffffffu, s, o);
    const float wn = e / s;

    const float ov = __ldg(off + bl * 256 + h * 32 + lane);
    const float rv = (lane < 8) ? __ldg(ref + bl * 8 + lane) : 0.f;

    const int Hs[4] = {128, 64, 32, 16};
    const int Ss[4] = {0, 16384, 20480, 21504};

    float acc = 0.f;
#pragma unroll
    for (int l = 0; l < 4; l++) {
        const int   Wl = Hs[l];
        const float fW = (float)Wl;
        const float rx = __shfl_sync(0xffffffffu, rv, 2 * l);
        const float ry = __shfl_sync(0xffffffffu, rv, 2 * l + 1);
        const bf16* vb = value + (b * LEN + Ss[l]) * 256 + h * 32 + lane;
#pragma unroll
        for (int p = 0; p < 4; p++) {
            const float ox = __shfl_sync(0xffffffffu, ov, l * 8 + p * 2);
            const float oy = __shfl_sync(0xffffffffu, ov, l * 8 + p * 2 + 1);
            const float aw = __shfl_sync(0xffffffffu, wn, l * 4 + p);
            const float x  = fmaf(rx, fW, ox) - 0.5f;
            const float y  = fmaf(ry, fW, oy) - 0.5f;
            const float x0f = floorf(x), y0f = floorf(y);
            const float dx = x - x0f, dy = y - y0f;
            const int   x0 = (int)x0f, y0 = (int)y0f;

            float psum = 0.f;
#pragma unroll
            for (int c = 0; c < 4; c++) {
                const int xi = x0 + (c & 1);
                const int yi = y0 + (c >> 1);
                const float cw = ((c & 1) ? dx : 1.f - dx) * ((c >> 1) ? dy : 1.f - dy);
                const bool valid = (xi >= 0) & (xi < Wl) & (yi >= 0) & (yi < Wl);
                const int xc = min(max(xi, 0), Wl - 1);
                const int yc = min(max(yi, 0), Wl - 1);
                const float v = __bfloat162float(vb[(yc * Wl + xc) * 256]);
                psum = fmaf(v, valid ? cw : 0.f, psum);
            }
            acc = fmaf(aw, psum, acc);
        }
    }
    out[bl * 256 + h * 32 + lane] = __float2bfloat16(acc);
}

// ---------------------------------------------------------------------------
// LayerNorm over 256 channels of (a + b): one warp per token.
// Writes fp32 out, optional bf16 copy.
// ---------------------------------------------------------------------------
__global__ __launch_bounds__(256)
void ln_kernel(const float* __restrict__ a, const float* __restrict__ b,
               const float* __restrict__ g, const float* __restrict__ beta,
               float* __restrict__ out, bf16* __restrict__ outb)
{
    const int tok  = (blockIdx.x * blockDim.x + threadIdx.x) >> 5;
    const int lane = threadIdx.x & 31;
    if (tok >= MTOK) return;

    const float* pa = a + (size_t)tok * 256;
    const float* pb = b + (size_t)tok * 256;
    float v[8];
    float sum = 0.f;
#pragma unroll
    for (int i = 0; i < 8; i++) {
        const int c = lane + i * 32;
        v[i] = pa[c] + pb[c];
        sum += v[i];
    }
#pragma unroll
    for (int o = 16; o > 0; o >>= 1) sum += __shfl_xor_sync(0xffffffffu, sum, o);
    const float mean = sum * (1.f / 256.f);

    float vs = 0.f;
#pragma unroll
    for (int i = 0; i < 8; i++) { const float d = v[i] - mean; vs += d * d; }
#pragma unroll
    for (int o = 16; o > 0; o >>= 1) vs += __shfl_xor_sync(0xffffffffu, vs, o);
    const float rinv = rsqrtf(vs * (1.f / 256.f) + LNEPS);

#pragma unroll
    for (int i = 0; i < 8; i++) {
        const int c = lane + i * 32;
        const float r = (v[i] - mean) * rinv * g[c] + beta[c];
        out[(size_t)tok * 256 + c] = r;
        if (outb) outb[(size_t)tok * 256 + c] = __float2bfloat16(r);
    }
}

// ---------------------------------------------------------------------------
// Launch
// ---------------------------------------------------------------------------
extern "C" void kernel_launch(void* const* d_in, const int* in_sizes, int n_in,
                              void* d_out, int out_size)
{
    const float* src  = (const float*)d_in[0];
    const float* pos  = (const float*)d_in[1];
    const float* ref  = (const float*)d_in[2];
    const unsigned char* mask = (const unsigned char*)d_in[5];
    const float* w_off  = (const float*)d_in[6];
    const float* b_off  = (const float*)d_in[7];
    const float* w_attn = (const float*)d_in[8];
    const float* b_attn = (const float*)d_in[9];
    const float* w_val  = (const float*)d_in[10];
    const float* b_val  = (const float*)d_in[11];
    const float* w_out  = (const float*)d_in[12];
    const float* b_out  = (const float*)d_in[13];
    const float* ln1g   = (const float*)d_in[14];
    const float* ln1b   = (const float*)d_in[15];
    const float* w1     = (const float*)d_in[16];
    const float* b1     = (const float*)d_in[17];
    const float* w2     = (const float*)d_in[18];
    const float* b2     = (const float*)d_in[19];
    const float* ln2g   = (const float*)d_in[20];
    const float* ln2b   = (const float*)d_in[21];
    float* out = (float*)d_out;

    bf16 *p_srcb, *p_qb, *p_value, *p_samp, *p_xb, *p_h;
    float *p_off, *p_attn, *p_x, *p_y;
    bf16 *t_val, *t_off, *t_attn, *t_out, *t_w1, *t_w2;
    cudaGetSymbolAddress((void**)&p_srcb,  g_srcb);
    cudaGetSymbolAddress((void**)&p_qb,    g_qb);
    cudaGetSymbolAddress((void**)&p_value, g_value);
    cudaGetSymbolAddress((void**)&p_off,   g_off);
    cudaGetSymbolAddress((void**)&p_attn,  g_attn);
    cudaGetSymbolAddress((void**)&p_samp,  g_samp);
    cudaGetSymbolAddress((void**)&p_x,     g_x);
    cudaGetSymbolAddress((void**)&p_xb,    g_xb);
    cudaGetSymbolAddress((void**)&p_y,     g_y);
    cudaGetSymbolAddress((void**)&p_h,     g_h);
    cudaGetSymbolAddress((void**)&t_val,   g_wtval);
    cudaGetSymbolAddress((void**)&t_off,   g_wtoff);
    cudaGetSymbolAddress((void**)&t_attn,  g_wtattn);
    cudaGetSymbolAddress((void**)&t_out,   g_wtout);
    cudaGetSymbolAddress((void**)&t_w1,    g_wt1);
    cudaGetSymbolAddress((void**)&t_w2,    g_wt2);

    const int SMEM = 2 * 2 * 128 * LDT * 2;   // 73728 bytes
    cudaFuncSetAttribute(gemm_bf, cudaFuncAttributeMaxDynamicSharedMemorySize, SMEM);

    const int MY = MTOK / 128;   // 340
    dim3 tb(32, 8);

    // srcb = bf16(src); qb = bf16(src + pos)
    prep_kernel<<<(MTOK * 256 / 4 + 255) / 256, 256>>>(src, pos, p_srcb, p_qb, MTOK * 256 / 4);

    // transpose + convert weights to K-major bf16 [N, K]
    transpose_w<<<dim3(256/32, 256/32), tb>>>(w_val,  t_val,  256, 256);
    transpose_w<<<dim3(256/32, 256/32), tb>>>(w_off,  t_off,  256, 256);
    transpose_w<<<dim3(128/32, 256/32), tb>>>(w_attn, t_attn, 256, 128);
    transpose_w<<<dim3(256/32, 256/32), tb>>>(w_out,  t_out,  256, 256);
    transpose_w<<<dim3(1024/32, 256/32), tb>>>(w1,    t_w1,   256, 1024);
    transpose_w<<<dim3(256/32, 1024/32), tb>>>(w2,    t_w2,   1024, 256);

    // value = srcb @ w_val + b_val (masked rows -> 0), bf16 out
    gemm_bf<<<dim3(2, MY), 256, SMEM>>>(p_srcb, t_val, b_val, mask, nullptr, p_value, 256, 256, 0);
    // off = q @ w_off + b_off (fp32 out)
    gemm_bf<<<dim3(2, MY), 256, SMEM>>>(p_qb, t_off, b_off, nullptr, p_off, nullptr, 256, 256, 0);
    // attn logits = q @ w_attn + b_attn (fp32 out)
    gemm_bf<<<dim3(1, MY), 256, SMEM>>>(p_qb, t_attn, b_attn, nullptr, p_attn, nullptr, 256, 128, 0);
    // deformable sampling (softmax fused), bf16 in/out
    samp_kernel<<<(MTOK * NHEADS) / 8, 256>>>(p_value, p_attn, p_off, ref, p_samp);
    // attn_out = samp @ w_out + b_out (fp32 out)
    gemm_bf<<<dim3(2, MY), 256, SMEM>>>(p_samp, t_out, b_out, nullptr, p_y, nullptr, 256, 256, 0);
    // x = LN(src + attn_out): fp32 + bf16
    ln_kernel<<<MTOK / 8, 256>>>(src, p_y, ln1g, ln1b, p_x, p_xb);
    // h = relu(xb @ w1 + b1), bf16 out
    gemm_bf<<<dim3(8, MY), 256, SMEM>>>(p_xb, t_w1, b1, nullptr, nullptr, p_h, 256, 1024, 1);
    // y = h @ w2 + b2 (fp32 out)
    gemm_bf<<<dim3(2, MY), 256, SMEM>>>(p_h, t_w2, b2, nullptr, p_y, nullptr, 1024, 256, 0);
    // out = LN(x + y)
    ln_kernel<<<MTOK / 8, 256>>>(p_x, p_y, ln2g, ln2b, out, nullptr);
}